// round 11
// baseline (speedup 1.0000x reference)
#include <cuda_runtime.h>

#define BATCH 1024
#define SEQ 32
#define DM 64
#define NL 4
#define DIN 128
#define XST 132   // padded float stride for xc rows
#define WST 68    // stride for in_proj weight rows (64 + 4)
#define XPS 132   // stride for xproj weight rows
#define OPS 132   // stride for out_proj weight rows (mult of 4 for float4)
#define WBN 17408 // wbuf floats = 256*68 (also holds 2x 4096 scan planes)
#define NT 256

typedef unsigned long long u64;

// ---- packed f32x2 helpers (sm_100+) ----
__device__ __forceinline__ u64 fma2(u64 a, u64 b, u64 c) {
    u64 d; asm("fma.rn.f32x2 %0, %1, %2, %3;" : "=l"(d) : "l"(a), "l"(b), "l"(c));
    return d;
}
__device__ __forceinline__ u64 mul2(u64 a, u64 b) {
    u64 d; asm("mul.rn.f32x2 %0, %1, %2;" : "=l"(d) : "l"(a), "l"(b));
    return d;
}
__device__ __forceinline__ u64 pk2(float lo, float hi) {
    u64 r; asm("mov.b64 %0, {%1, %2};" : "=l"(r) : "f"(lo), "f"(hi));
    return r;
}
__device__ __forceinline__ float hadd2(u64 v) {
    float lo, hi;
    asm("mov.b64 {%0, %1}, %2;" : "=f"(lo), "=f"(hi) : "l"(v));
    return lo + hi;
}

// Fused embedding parameters (computed once per launch by setup_kernel):
__device__ float g_W1[64];
__device__ float g_W2[64];
__device__ float g_Bc[64];
__device__ float g_E[2][64];
__device__ int   g_Afast;   // 1 if A_log == log(1..16) broadcast (integer A)

__global__ void setup_kernel(const float* __restrict__ inw,
                             const float* __restrict__ inb,
                             const float* __restrict__ l1w,
                             const float* __restrict__ l1b,
                             const float* __restrict__ l2w,
                             const float* __restrict__ l2b,
                             const float* __restrict__ emb,
                             const float* __restrict__ alog) {
    __shared__ int sbad;
    int c = threadIdx.x;
    if (c == 0) sbad = 0;
    __syncthreads();
    int bad = 0;
    for (int idx = c; idx < NL * 2 * DIN * 16; idx += 64) {
        int i = idx & 15;
        if (fabsf(alog[idx] - __logf((float)(i + 1))) > 1e-4f) bad = 1;
    }
    if (bad) atomicExch(&sbad, 1);
    __syncthreads();
    if (c == 0) g_Afast = sbad ? 0 : 1;

    if (c >= 64) return;
    const float* row = inw + c * 192;   // in_w is (64, 192) row-major
    float w1 = 0.f, w2 = 0.f, bb = inb[c], e0 = 0.f, e1 = 0.f;
    for (int k = 0; k < 64; k++) {
        float r0 = row[k], r1 = row[64 + k], r2 = row[128 + k];
        w1 += r0 * l1w[k];
        w2 += r1 * l2w[k];
        bb += r0 * l1b[k] + r1 * l2b[k];
        e0 += r2 * emb[k];
        e1 += r2 * emb[64 + k];
    }
    g_W1[c] = w1; g_W2[c] = w2; g_Bc[c] = bb;
    g_E[0][c] = e0; g_E[1][c] = e1;
}

struct SmemT {
    float wbuf[WBN];        // staged weights / scan partial planes (2x 32*128)
    float xe[SEQ][DM];      // running residual stream
    float hln[SEQ][DM];     // layernormed input (shared by both dirs)
    float xc[SEQ][XST];     // raw x -> conv+silu x -> gated y' (in place)
    float dbl[SEQ][36];     // xproj output: [dt_r(4) | B(16) | C(16)]
    float ob[SEQ];
    int   fz[SEQ];
    float snr;
};

__device__ __forceinline__ float d4(float4 a, float4 b) {
    return a.x * b.x + a.y * b.y + a.z * b.z + a.w * b.w;
}
__device__ __forceinline__ float sigf(float x) {
    return __fdividef(1.f, 1.f + __expf(-x));
}
__device__ __forceinline__ float siluf(float x) { return x * sigf(x); }

__global__ __launch_bounds__(NT, 2) void mamba_kernel(
    const float* __restrict__ ob, const float* __restrict__ snr,
    const int* __restrict__ fz,
    const float* __restrict__ blnw, const float* __restrict__ blnb,
    const float* __restrict__ inproj, const float* __restrict__ convw,
    const float* __restrict__ convb, const float* __restrict__ xprojw,
    const float* __restrict__ dtw, const float* __restrict__ dtb,
    const float* __restrict__ alog, const float* __restrict__ Dp,
    const float* __restrict__ outw,
    const float* __restrict__ pw, const float* __restrict__ pb,
    const float* __restrict__ fw, const float* __restrict__ fb,
    float* __restrict__ out) {
    extern __shared__ unsigned char smem_raw[];
    SmemT& s = *reinterpret_cast<SmemT*>(smem_raw);

    const int tid = threadIdx.x;
    const int b = blockIdx.x;
    const int d = tid & 127;       // scan: channel (0..127)
    const int half = tid >> 7;     // scan: state half
    const int c2 = tid & 63;       // in_proj/conv/gate: channels c2, c2+64
    const int qt = tid >> 6;       // in_proj/conv/gate: time quarter (8 t's)
    const int tq0 = qt << 3;
    const int r8 = tid >> 3;       // LN row (0..31)
    const int q8 = tid & 7;        // LN lane within row
    const int afast = g_Afast;

    // ---- Phase 0: embedding -> xe ----
    if (tid < 32) {
        s.ob[tid] = ob[b * SEQ + tid];
        s.fz[tid] = fz[b * SEQ + tid];
    }
    if (tid == 0) s.snr = snr[b];
    __syncthreads();
#pragma unroll
    for (int i = 0; i < 8; i++) {
        int o = tid + i * NT;
        int t = o >> 6, c = o & 63;
        s.xe[t][c] = s.ob[t] * g_W1[c] + s.snr * g_W2[c] + g_E[s.fz[t]][c] + g_Bc[c];
    }
    __syncthreads();

    for (int l = 0; l < NL; l++) {
        // ---- LayerNorm: 8 threads per row, 8 elems each ----
        {
            float v[8];
            const float* xr = s.xe[r8];
#pragma unroll
            for (int k = 0; k < 8; k++) v[k] = xr[q8 * 8 + k];
            float sum = 0.f;
#pragma unroll
            for (int k = 0; k < 8; k++) sum += v[k];
            sum += __shfl_xor_sync(0xffffffffu, sum, 1);
            sum += __shfl_xor_sync(0xffffffffu, sum, 2);
            sum += __shfl_xor_sync(0xffffffffu, sum, 4);
            float m = sum * (1.f / 64.f);
            float var = 0.f;
#pragma unroll
            for (int k = 0; k < 8; k++) { float dd = v[k] - m; var += dd * dd; }
            var += __shfl_xor_sync(0xffffffffu, var, 1);
            var += __shfl_xor_sync(0xffffffffu, var, 2);
            var += __shfl_xor_sync(0xffffffffu, var, 4);
            float rstd = rsqrtf(var * (1.f / 64.f) + 1e-5f);
            const float* lw = blnw + l * 64;
            const float* lb = blnb + l * 64;
#pragma unroll
            for (int k = 0; k < 8; k++) {
                int kk = q8 * 8 + k;
                s.hln[r8][kk] = (v[k] - m) * rstd * lw[kk] + lb[kk];
            }
        }
        __syncthreads();

        for (int dir = 0; dir < 2; dir++) {
            const int ld = l * 2 + dir;
            float az0[8], az1[8];   // z columns (2 ch x 8 t), regs until gate
            float ax0[8], ax1[8];   // raw x columns

            // ---- stage Wx+Wz (256 rows x 64) into wbuf[row][WST] ----
            {
                const float4* g = (const float4*)(inproj + ld * 256 * 64);
#pragma unroll
                for (int i = 0; i < 16; i++) {
                    int gi = tid + i * NT;           // 0..4095
                    int rr = gi >> 4, j = gi & 15;
                    *(float4*)&s.wbuf[rr * WST + 4 * j] = g[gi];
                }
            }
            __syncthreads();

            // ---- fused in_proj (packed f32x2): 2 ch x 8 t, x and z ----
            {
                u64 axp0[8], axp1[8], azp0[8], azp1[8];
#pragma unroll
                for (int tt = 0; tt < 8; tt++) {
                    axp0[tt] = 0ULL; axp1[tt] = 0ULL;
                    azp0[tt] = 0ULL; azp1[tt] = 0ULL;
                }
                const ulonglong2* Wx0 = (const ulonglong2*)&s.wbuf[c2 * WST];
                const ulonglong2* Wx1 = (const ulonglong2*)&s.wbuf[(c2 + 64) * WST];
                const ulonglong2* Wz0 = (const ulonglong2*)&s.wbuf[(128 + c2) * WST];
                const ulonglong2* Wz1 = (const ulonglong2*)&s.wbuf[(192 + c2) * WST];
#pragma unroll
                for (int k0 = 0; k0 < 16; k0++) {
                    ulonglong2 wx0 = Wx0[k0];
                    ulonglong2 wx1 = Wx1[k0];
                    ulonglong2 wz0 = Wz0[k0];
                    ulonglong2 wz1 = Wz1[k0];
#pragma unroll
                    for (int tt = 0; tt < 8; tt++) {
                        int t = tq0 + tt;
                        int rt = dir ? (31 - t) : t;
                        ulonglong2 h = *(const ulonglong2*)&s.hln[rt][4 * k0];  // broadcast
                        axp0[tt] = fma2(h.x, wx0.x, axp0[tt]);
                        axp0[tt] = fma2(h.y, wx0.y, axp0[tt]);
                        axp1[tt] = fma2(h.x, wx1.x, axp1[tt]);
                        axp1[tt] = fma2(h.y, wx1.y, axp1[tt]);
                        azp0[tt] = fma2(h.x, wz0.x, azp0[tt]);
                        azp0[tt] = fma2(h.y, wz0.y, azp0[tt]);
                        azp1[tt] = fma2(h.x, wz1.x, azp1[tt]);
                        azp1[tt] = fma2(h.y, wz1.y, azp1[tt]);
                    }
                }
#pragma unroll
                for (int tt = 0; tt < 8; tt++) {
                    ax0[tt] = hadd2(axp0[tt]);
                    ax1[tt] = hadd2(axp1[tt]);
                    az0[tt] = hadd2(azp0[tt]);
                    az1[tt] = hadd2(azp1[tt]);
                }
                // publish raw x for cross-quarter conv boundary
#pragma unroll
                for (int tt = 0; tt < 8; tt++) {
                    s.xc[tq0 + tt][c2] = ax0[tt];
                    s.xc[tq0 + tt][c2 + 64] = ax1[tt];
                }
            }
            __syncthreads();

            // ---- read conv boundary preds (raw values of prev quarter) ----
            float pa0 = 0.f, pa1 = 0.f, pa2 = 0.f;   // channel c2
            float pb0 = 0.f, pb1 = 0.f, pb2 = 0.f;   // channel c2+64
            if (qt) {
                pa0 = s.xc[tq0 - 3][c2]; pa1 = s.xc[tq0 - 2][c2]; pa2 = s.xc[tq0 - 1][c2];
                pb0 = s.xc[tq0 - 3][c2 + 64]; pb1 = s.xc[tq0 - 2][c2 + 64]; pb2 = s.xc[tq0 - 1][c2 + 64];
            }
            __syncthreads();

            // ---- conv (k=4) + bias + silu, write in place; stage xproj wts ----
            {
                float4 cwa = *(const float4*)(convw + (ld * 128 + c2) * 4);
                float4 cwb = *(const float4*)(convw + (ld * 128 + c2 + 64) * 4);
                float cba = convb[ld * 128 + c2];
                float cbb = convb[ld * 128 + c2 + 64];
#pragma unroll
                for (int tt = 0; tt < 8; tt++) {
                    float ra = ax0[tt], rb = ax1[tt];
                    float va = cba + cwa.x * pa0 + cwa.y * pa1 + cwa.z * pa2 + cwa.w * ra;
                    float vb = cbb + cwb.x * pb0 + cwb.y * pb1 + cwb.z * pb2 + cwb.w * rb;
                    s.xc[tq0 + tt][c2] = siluf(va);
                    s.xc[tq0 + tt][c2 + 64] = siluf(vb);
                    pa0 = pa1; pa1 = pa2; pa2 = ra;
                    pb0 = pb1; pb1 = pb2; pb2 = rb;
                }
            }
            {
                const float4* g = (const float4*)(xprojw + ld * 36 * 128);
#pragma unroll
                for (int i = 0; i < 5; i++) {
                    int gi = tid + i * NT;           // 0..1279, guard 1152
                    if (gi < 1152) {
                        int j = gi >> 5, kq = gi & 31;
                        *(float4*)&s.wbuf[j * XPS + 4 * kq] = g[gi];
                    }
                }
            }
            __syncthreads();

            // ---- xproj (packed): warp owns j-set, lane owns t ----
            {
                const int w = tid >> 5;      // 0..7 (warp id)
                const int lt = tid & 31;     // lane = t
                u64 acc2[5] = {0ULL, 0ULL, 0ULL, 0ULL, 0ULL};
#pragma unroll 8
                for (int k0 = 0; k0 < 32; k0++) {
                    ulonglong2 xv = *(const ulonglong2*)&s.xc[lt][4 * k0];
#pragma unroll
                    for (int i = 0; i < 5; i++) {
                        ulonglong2 wv = *(const ulonglong2*)&s.wbuf[(w + 8 * i) * XPS + 4 * k0];
                        acc2[i] = fma2(xv.x, wv.x, acc2[i]);
                        acc2[i] = fma2(xv.y, wv.y, acc2[i]);
                    }
                }
#pragma unroll
                for (int i = 0; i < 5; i++) {
                    int j = w + 8 * i;
                    if (j < 36) s.dbl[lt][j] = hadd2(acc2[i]);
                }
            }
            __syncthreads();

            // ---- fused dt + scan (packed state pairs) ----
            {
                const int si0 = half * 8;
                float4 dwv = *(const float4*)(dtw + (ld * 128 + d) * 4);
                float dtbv = dtb[ld * 128 + d];
                float* plane = &s.wbuf[half * 4096];

                if (afast) {
                    // A[i] = -(i+1): dA_i = r^(si0+1+i), r = exp(-dtv)
                    u64 h01 = 0ULL, h23 = 0ULL, h45 = 0ULL, h67 = 0ULL;
                    for (int t = 0; t < SEQ; t++) {
                        float4 dr = *(const float4*)(&s.dbl[t][0]);
                        float u = d4(dr, dwv) + dtbv;
                        float dtv = (u > 20.f) ? u : __logf(1.f + __expf(u));
                        float x = s.xc[t][d];
                        float dtx = dtv * x;
                        float r = __expf(-dtv);
                        float r2s = r * r;
                        u64 r2 = pk2(r2s, r2s);
                        u64 dtx2 = pk2(dtx, dtx);
                        u64 p;
                        if (half == 0) {
                            p = pk2(r, r2s);             // (r^1, r^2)
                        } else {
                            float r4 = r2s * r2s, r8 = r4 * r4;
                            p = pk2(r8 * r, r8 * r2s);   // (r^9, r^10)
                        }
                        ulonglong2 Bv  = *(const ulonglong2*)&s.dbl[t][4 + si0];
                        ulonglong2 Bv2 = *(const ulonglong2*)&s.dbl[t][8 + si0];
                        ulonglong2 Cv  = *(const ulonglong2*)&s.dbl[t][20 + si0];
                        ulonglong2 Cv2 = *(const ulonglong2*)&s.dbl[t][24 + si0];
                        u64 y2 = 0ULL;
                        h01 = fma2(p, h01, mul2(dtx2, Bv.x));
                        y2 = fma2(h01, Cv.x, y2);
                        p = mul2(p, r2);
                        h23 = fma2(p, h23, mul2(dtx2, Bv.y));
                        y2 = fma2(h23, Cv.y, y2);
                        p = mul2(p, r2);
                        h45 = fma2(p, h45, mul2(dtx2, Bv2.x));
                        y2 = fma2(h45, Cv2.x, y2);
                        p = mul2(p, r2);
                        h67 = fma2(p, h67, mul2(dtx2, Bv2.y));
                        y2 = fma2(h67, Cv2.y, y2);
                        plane[t * 128 + d] = hadd2(y2);   // partial over 8 states
                    }
                } else {
                    // generic A fallback (scalar)
                    const float* ar = alog + (ld * 128 + d) * 16 + si0;
                    float a[8];
#pragma unroll
                    for (int si = 0; si < 8; si += 4) {
                        float4 av = *(const float4*)(ar + si);
                        a[si] = -__expf(av.x); a[si + 1] = -__expf(av.y);
                        a[si + 2] = -__expf(av.z); a[si + 3] = -__expf(av.w);
                    }
                    float h[8];
#pragma unroll
                    for (int si = 0; si < 8; si++) h[si] = 0.f;
                    for (int t = 0; t < SEQ; t++) {
                        float4 dr = *(const float4*)(&s.dbl[t][0]);
                        float u = d4(dr, dwv) + dtbv;
                        float dtv = (u > 20.f) ? u : __logf(1.f + __expf(u));
                        float x = s.xc[t][d];
                        float dtx = dtv * x;
                        float4 B0 = *(const float4*)(&s.dbl[t][4 + si0]);
                        float4 B1 = *(const float4*)(&s.dbl[t][8 + si0]);
                        float4 C0 = *(const float4*)(&s.dbl[t][20 + si0]);
                        float4 C1 = *(const float4*)(&s.dbl[t][24 + si0]);
                        float y = 0.f;
#define SSTEP(i, Bv_, Cv_)                                      \
    h[i] = __expf(dtv * a[i]) * h[i] + dtx * (Bv_);             \
    y += h[i] * (Cv_);
                        SSTEP(0, B0.x, C0.x)  SSTEP(1, B0.y, C0.y)
                        SSTEP(2, B0.z, C0.z)  SSTEP(3, B0.w, C0.w)
                        SSTEP(4, B1.x, C1.x)  SSTEP(5, B1.y, C1.y)
                        SSTEP(6, B1.z, C1.z)  SSTEP(7, B1.w, C1.w)
#undef SSTEP
                        plane[t * 128 + d] = y;
                    }
                }
            }
            __syncthreads();

            // ---- finalize in (c2,qt) mapping: combine halves, D*x, gate ----
            {
                float D0 = Dp[ld * 128 + c2];
                float D1 = Dp[ld * 128 + c2 + 64];
#pragma unroll
                for (int tt = 0; tt < 8; tt++) {
                    int t = tq0 + tt;
                    float y0 = s.wbuf[t * 128 + c2] + s.wbuf[4096 + t * 128 + c2];
                    float y1 = s.wbuf[t * 128 + c2 + 64] + s.wbuf[4096 + t * 128 + c2 + 64];
                    float x0 = s.xc[t][c2];
                    float x1 = s.xc[t][c2 + 64];
                    s.xc[t][c2] = (y0 + D0 * x0) * siluf(az0[tt]);
                    s.xc[t][c2 + 64] = (y1 + D1 * x1) * siluf(az1[tt]);
                }
            }
            __syncthreads();

            // ---- stage out_proj weights [64][128] -> wbuf[c][OPS] ----
            {
                const float4* g = (const float4*)(outw + ld * 64 * 128);
#pragma unroll
                for (int i = 0; i < 8; i++) {
                    int gi = tid + i * NT;           // 0..2047
                    int c = gi >> 5, kq = gi & 31;
                    *(float4*)&s.wbuf[c * OPS + 4 * kq] = g[gi];
                }
            }
            __syncthreads();

            // ---- out_proj (packed): 2 c's (lane, lane+32) x 4 t's ----
            {
                const int tq = tid >> 5;             // 0..7, warp-uniform
                const int c0 = tid & 31;             // bank step 4 at stride 132
                const int c1 = c0 + 32;
                u64 a0[4] = {0ULL, 0ULL, 0ULL, 0ULL};
                u64 a1[4] = {0ULL, 0ULL, 0ULL, 0ULL};
                const ulonglong2* W0 = (const ulonglong2*)&s.wbuf[c0 * OPS];
                const ulonglong2* W1 = (const ulonglong2*)&s.wbuf[c1 * OPS];
#pragma unroll 8
                for (int k0 = 0; k0 < 32; k0++) {
                    ulonglong2 w0 = W0[k0];
                    ulonglong2 w1 = W1[k0];
#pragma unroll
                    for (int tt = 0; tt < 4; tt++) {
                        ulonglong2 yv = *(const ulonglong2*)&s.xc[tq * 4 + tt][4 * k0];
                        a0[tt] = fma2(w0.x, yv.x, a0[tt]);
                        a0[tt] = fma2(w0.y, yv.y, a0[tt]);
                        a1[tt] = fma2(w1.x, yv.x, a1[tt]);
                        a1[tt] = fma2(w1.y, yv.y, a1[tt]);
                    }
                }
#pragma unroll
                for (int tt = 0; tt < 4; tt++) {
                    int t = tq * 4 + tt;
                    int rt = dir ? (31 - t) : t;
                    s.xe[rt][c0] += hadd2(a0[tt]);   // unique (rt,c) owner
                    s.xe[rt][c1] += hadd2(a1[tt]);
                }
            }
            __syncthreads();
        }
    }

    // ---- final: x = xe + x0 (recomputed), post-LN, project to scalar ----
    {
        float obr = s.ob[r8];
        float snrv = s.snr;
        int fzr = s.fz[r8];
        float v[8];
#pragma unroll
        for (int k = 0; k < 8; k++) {
            int kk = q8 * 8 + k;
            float x0v = obr * g_W1[kk] + snrv * g_W2[kk] + g_E[fzr][kk] + g_Bc[kk];
            v[k] = s.xe[r8][kk] + x0v;
        }
        float sum = 0.f;
#pragma unroll
        for (int k = 0; k < 8; k++) sum += v[k];
        sum += __shfl_xor_sync(0xffffffffu, sum, 1);
        sum += __shfl_xor_sync(0xffffffffu, sum, 2);
        sum += __shfl_xor_sync(0xffffffffu, sum, 4);
        float m = sum * (1.f / 64.f);
        float var = 0.f;
#pragma unroll
        for (int k = 0; k < 8; k++) { float dd = v[k] - m; var += dd * dd; }
        var += __shfl_xor_sync(0xffffffffu, var, 1);
        var += __shfl_xor_sync(0xffffffffu, var, 2);
        var += __shfl_xor_sync(0xffffffffu, var, 4);
        float rstd = rsqrtf(var * (1.f / 64.f) + 1e-5f);
        float acc = 0.f;
#pragma unroll
        for (int k = 0; k < 8; k++) {
            int kk = q8 * 8 + k;
            acc += ((v[k] - m) * rstd * pw[kk] + pb[kk]) * fw[kk];
        }
        acc += __shfl_xor_sync(0xffffffffu, acc, 1);
        acc += __shfl_xor_sync(0xffffffffu, acc, 2);
        acc += __shfl_xor_sync(0xffffffffu, acc, 4);
        if (q8 == 0) out[b * SEQ + r8] = acc + fb[0];
    }
}

extern "C" void kernel_launch(void* const* d_in, const int* in_sizes, int n_in,
                              void* d_out, int out_size) {
    // Disambiguate input ordering:
    //  dict order:      [ch, snr, frozen, emb, ...]  -> in_sizes[2] == 32768
    //  signature order: [ch, snr, emb, ..., frozen]  -> in_sizes[2] == 128
    const bool dictOrder = (in_sizes[2] == BATCH * SEQ);
    const int i_ch = 0, i_snr = 1;
    const int i_fz = dictOrder ? 2 : 24;
    const int base = dictOrder ? 3 : 2;
    const int i_emb = base + 0, i_l1w = base + 1, i_l1b = base + 2;
    const int i_l2w = base + 3, i_l2b = base + 4;
    const int i_inw = base + 5, i_inb = base + 6;
    const int i_blnw = base + 7, i_blnb = base + 8;
    const int i_inproj = base + 9, i_convw = base + 10, i_convb = base + 11;
    const int i_xproj = base + 12, i_dtw = base + 13, i_dtb = base + 14;
    const int i_alog = base + 15, i_D = base + 16, i_outproj = base + 17;
    const int i_pw = base + 18, i_pb = base + 19;
    const int i_fw = base + 20, i_fb = base + 21;

    const float* f_ch = (const float*)d_in[i_ch];
    const float* f_snr = (const float*)d_in[i_snr];
    const int* f_fz = (const int*)d_in[i_fz];

    setup_kernel<<<1, 64>>>(
        (const float*)d_in[i_inw], (const float*)d_in[i_inb],
        (const float*)d_in[i_l1w], (const float*)d_in[i_l1b],
        (const float*)d_in[i_l2w], (const float*)d_in[i_l2b],
        (const float*)d_in[i_emb], (const float*)d_in[i_alog]);

    size_t shbytes = sizeof(SmemT);
    cudaFuncSetAttribute(mamba_kernel,
                         cudaFuncAttributeMaxDynamicSharedMemorySize,
                         (int)shbytes);

    mamba_kernel<<<BATCH, NT, shbytes>>>(
        f_ch, f_snr, f_fz,
        (const float*)d_in[i_blnw], (const float*)d_in[i_blnb],
        (const float*)d_in[i_inproj], (const float*)d_in[i_convw],
        (const float*)d_in[i_convb], (const float*)d_in[i_xproj],
        (const float*)d_in[i_dtw], (const float*)d_in[i_dtb],
        (const float*)d_in[i_alog], (const float*)d_in[i_D],
        (const float*)d_in[i_outproj],
        (const float*)d_in[i_pw], (const float*)d_in[i_pb],
        (const float*)d_in[i_fw], (const float*)d_in[i_fb],
        (float*)d_out);
}

// round 12
// speedup vs baseline: 1.5402x; 1.5402x over previous
#include <cuda_runtime.h>

#define BATCH 1024
#define SEQ 32
#define DM 64
#define NL 4
#define DIN 128
#define XST 132   // padded float stride for xc rows
#define WST 68    // stride for in_proj weight rows (64 + 4)
#define XPS 132   // stride for xproj weight rows
#define OPS 132   // stride for out_proj weight rows (mult of 4 for float4)
#define WBN 17408 // wbuf floats = 256*68 (also holds 2x 4096 scan planes)
#define NT 256

typedef unsigned long long u64;

// ---- packed f32x2 helpers (sm_100+) ----
__device__ __forceinline__ u64 fma2(u64 a, u64 b, u64 c) {
    u64 d; asm("fma.rn.f32x2 %0, %1, %2, %3;" : "=l"(d) : "l"(a), "l"(b), "l"(c));
    return d;
}
__device__ __forceinline__ float hadd2(u64 v) {
    float lo, hi;
    asm("mov.b64 {%0, %1}, %2;" : "=f"(lo), "=f"(hi) : "l"(v));
    return lo + hi;
}

// Fused embedding parameters (computed once per launch by setup_kernel):
__device__ float g_W1[64];
__device__ float g_W2[64];
__device__ float g_Bc[64];
__device__ float g_E[2][64];
__device__ int   g_Afast;   // 1 if A_log == log(1..16) broadcast (integer A)

__global__ void setup_kernel(const float* __restrict__ inw,
                             const float* __restrict__ inb,
                             const float* __restrict__ l1w,
                             const float* __restrict__ l1b,
                             const float* __restrict__ l2w,
                             const float* __restrict__ l2b,
                             const float* __restrict__ emb,
                             const float* __restrict__ alog) {
    __shared__ int sbad;
    int c = threadIdx.x;
    if (c == 0) sbad = 0;
    __syncthreads();
    int bad = 0;
    for (int idx = c; idx < NL * 2 * DIN * 16; idx += 64) {
        int i = idx & 15;
        if (fabsf(alog[idx] - __logf((float)(i + 1))) > 1e-4f) bad = 1;
    }
    if (bad) atomicExch(&sbad, 1);
    __syncthreads();
    if (c == 0) g_Afast = sbad ? 0 : 1;

    if (c >= 64) return;
    const float* row = inw + c * 192;   // in_w is (64, 192) row-major
    float w1 = 0.f, w2 = 0.f, bb = inb[c], e0 = 0.f, e1 = 0.f;
    for (int k = 0; k < 64; k++) {
        float r0 = row[k], r1 = row[64 + k], r2 = row[128 + k];
        w1 += r0 * l1w[k];
        w2 += r1 * l2w[k];
        bb += r0 * l1b[k] + r1 * l2b[k];
        e0 += r2 * emb[k];
        e1 += r2 * emb[64 + k];
    }
    g_W1[c] = w1; g_W2[c] = w2; g_Bc[c] = bb;
    g_E[0][c] = e0; g_E[1][c] = e1;
}

struct SmemT {
    float wbuf[WBN];        // staged weights / scan partial planes (2x 32*128)
    float xe[SEQ][DM];      // running residual stream
    float hln[SEQ][DM];     // layernormed input (shared by both dirs)
    float xc[SEQ][XST];     // raw x -> conv+silu x -> gated y' (in place)
    float dbl[SEQ][36];     // xproj output: [dt_r(4) | B(16) | C(16)]
    float ob[SEQ];
    int   fz[SEQ];
    float snr;
};

__device__ __forceinline__ float d4(float4 a, float4 b) {
    return a.x * b.x + a.y * b.y + a.z * b.z + a.w * b.w;
}
__device__ __forceinline__ float sigf(float x) {
    return __fdividef(1.f, 1.f + __expf(-x));
}
__device__ __forceinline__ float siluf(float x) { return x * sigf(x); }

__global__ __launch_bounds__(NT, 2) void mamba_kernel(
    const float* __restrict__ ob, const float* __restrict__ snr,
    const int* __restrict__ fz,
    const float* __restrict__ blnw, const float* __restrict__ blnb,
    const float* __restrict__ inproj, const float* __restrict__ convw,
    const float* __restrict__ convb, const float* __restrict__ xprojw,
    const float* __restrict__ dtw, const float* __restrict__ dtb,
    const float* __restrict__ alog, const float* __restrict__ Dp,
    const float* __restrict__ outw,
    const float* __restrict__ pw, const float* __restrict__ pb,
    const float* __restrict__ fw, const float* __restrict__ fb,
    float* __restrict__ out) {
    extern __shared__ unsigned char smem_raw[];
    SmemT& s = *reinterpret_cast<SmemT*>(smem_raw);

    const int tid = threadIdx.x;
    const int b = blockIdx.x;
    const int d = tid & 127;       // scan: channel (0..127)
    const int half = tid >> 7;     // scan: state half
    const int c2 = tid & 63;       // in_proj/conv/gate: channels c2, c2+64
    const int qt = tid >> 6;       // in_proj/conv/gate: time quarter (8 t's)
    const int tq0 = qt << 3;
    const int r8 = tid >> 3;       // LN row (0..31)
    const int q8 = tid & 7;        // LN lane within row
    const int afast = g_Afast;

    // ---- Phase 0: embedding -> xe ----
    if (tid < 32) {
        s.ob[tid] = ob[b * SEQ + tid];
        s.fz[tid] = fz[b * SEQ + tid];
    }
    if (tid == 0) s.snr = snr[b];
    __syncthreads();
#pragma unroll
    for (int i = 0; i < 8; i++) {
        int o = tid + i * NT;
        int t = o >> 6, c = o & 63;
        s.xe[t][c] = s.ob[t] * g_W1[c] + s.snr * g_W2[c] + g_E[s.fz[t]][c] + g_Bc[c];
    }
    __syncthreads();

    for (int l = 0; l < NL; l++) {
        // ---- LayerNorm: 8 threads per row, 8 elems each ----
        {
            float v[8];
            const float* xr = s.xe[r8];
#pragma unroll
            for (int k = 0; k < 8; k++) v[k] = xr[q8 * 8 + k];
            float sum = 0.f;
#pragma unroll
            for (int k = 0; k < 8; k++) sum += v[k];
            sum += __shfl_xor_sync(0xffffffffu, sum, 1);
            sum += __shfl_xor_sync(0xffffffffu, sum, 2);
            sum += __shfl_xor_sync(0xffffffffu, sum, 4);
            float m = sum * (1.f / 64.f);
            float var = 0.f;
#pragma unroll
            for (int k = 0; k < 8; k++) { float dd = v[k] - m; var += dd * dd; }
            var += __shfl_xor_sync(0xffffffffu, var, 1);
            var += __shfl_xor_sync(0xffffffffu, var, 2);
            var += __shfl_xor_sync(0xffffffffu, var, 4);
            float rstd = rsqrtf(var * (1.f / 64.f) + 1e-5f);
            const float* lw = blnw + l * 64;
            const float* lb = blnb + l * 64;
#pragma unroll
            for (int k = 0; k < 8; k++) {
                int kk = q8 * 8 + k;
                s.hln[r8][kk] = (v[k] - m) * rstd * lw[kk] + lb[kk];
            }
        }
        __syncthreads();

        for (int dir = 0; dir < 2; dir++) {
            const int ld = l * 2 + dir;
            float az0[8], az1[8];   // z columns (2 ch x 8 t), regs until gate

            // ---- stage Wx+Wz (256 rows x 64) into wbuf[row][WST] ----
            {
                const float4* g = (const float4*)(inproj + ld * 256 * 64);
#pragma unroll
                for (int i = 0; i < 16; i++) {
                    int gi = tid + i * NT;           // 0..4095
                    int rr = gi >> 4, j = gi & 15;
                    *(float4*)&s.wbuf[rr * WST + 4 * j] = g[gi];
                }
            }
            __syncthreads();

            // ---- fused in_proj (scalar, proven R9 form): 2 ch x 8 t ----
            float ax0[8], ax1[8];
            {
#pragma unroll
                for (int tt = 0; tt < 8; tt++) {
                    ax0[tt] = 0.f; ax1[tt] = 0.f; az0[tt] = 0.f; az1[tt] = 0.f;
                }
                const float* Wx0 = &s.wbuf[c2 * WST];
                const float* Wx1 = &s.wbuf[(c2 + 64) * WST];
                const float* Wz0 = &s.wbuf[(128 + c2) * WST];
                const float* Wz1 = &s.wbuf[(192 + c2) * WST];
#pragma unroll
                for (int k0 = 0; k0 < 16; k0++) {
                    float4 wx0 = *(const float4*)(Wx0 + 4 * k0);
                    float4 wx1 = *(const float4*)(Wx1 + 4 * k0);
                    float4 wz0 = *(const float4*)(Wz0 + 4 * k0);
                    float4 wz1 = *(const float4*)(Wz1 + 4 * k0);
#pragma unroll
                    for (int tt = 0; tt < 8; tt++) {
                        int t = tq0 + tt;
                        int rt = dir ? (31 - t) : t;
                        float4 h = *(const float4*)&s.hln[rt][4 * k0];  // broadcast
                        ax0[tt] += d4(h, wx0);
                        ax1[tt] += d4(h, wx1);
                        az0[tt] += d4(h, wz0);
                        az1[tt] += d4(h, wz1);
                    }
                }
                // publish raw x for cross-quarter conv boundary
#pragma unroll
                for (int tt = 0; tt < 8; tt++) {
                    s.xc[tq0 + tt][c2] = ax0[tt];
                    s.xc[tq0 + tt][c2 + 64] = ax1[tt];
                }
            }
            __syncthreads();

            // ---- read conv boundary preds (raw values of prev quarter) ----
            float pa0 = 0.f, pa1 = 0.f, pa2 = 0.f;   // channel c2
            float pb0 = 0.f, pb1 = 0.f, pb2 = 0.f;   // channel c2+64
            if (qt) {
                pa0 = s.xc[tq0 - 3][c2]; pa1 = s.xc[tq0 - 2][c2]; pa2 = s.xc[tq0 - 1][c2];
                pb0 = s.xc[tq0 - 3][c2 + 64]; pb1 = s.xc[tq0 - 2][c2 + 64]; pb2 = s.xc[tq0 - 1][c2 + 64];
            }
            __syncthreads();

            // ---- conv (k=4) + bias + silu, write in place; stage xproj wts ----
            {
                float4 cwa = *(const float4*)(convw + (ld * 128 + c2) * 4);
                float4 cwb = *(const float4*)(convw + (ld * 128 + c2 + 64) * 4);
                float cba = convb[ld * 128 + c2];
                float cbb = convb[ld * 128 + c2 + 64];
#pragma unroll
                for (int tt = 0; tt < 8; tt++) {
                    float ra = ax0[tt], rb = ax1[tt];
                    float va = cba + cwa.x * pa0 + cwa.y * pa1 + cwa.z * pa2 + cwa.w * ra;
                    float vb = cbb + cwb.x * pb0 + cwb.y * pb1 + cwb.z * pb2 + cwb.w * rb;
                    s.xc[tq0 + tt][c2] = siluf(va);
                    s.xc[tq0 + tt][c2 + 64] = siluf(vb);
                    pa0 = pa1; pa1 = pa2; pa2 = ra;
                    pb0 = pb1; pb1 = pb2; pb2 = rb;
                }
            }
            {
                const float4* g = (const float4*)(xprojw + ld * 36 * 128);
#pragma unroll
                for (int i = 0; i < 5; i++) {
                    int gi = tid + i * NT;           // 0..1279, guard 1152
                    if (gi < 1152) {
                        int j = gi >> 5, kq = gi & 31;
                        *(float4*)&s.wbuf[j * XPS + 4 * kq] = g[gi];
                    }
                }
            }
            __syncthreads();

            // ---- xproj (packed f32x2, small acc state): warp owns j-set ----
            {
                const int w = tid >> 5;      // 0..7 (warp id)
                const int lt = tid & 31;     // lane = t
                u64 acc2[5] = {0ULL, 0ULL, 0ULL, 0ULL, 0ULL};
#pragma unroll 8
                for (int k0 = 0; k0 < 32; k0++) {
                    ulonglong2 xv = *(const ulonglong2*)&s.xc[lt][4 * k0];
#pragma unroll
                    for (int i = 0; i < 5; i++) {
                        ulonglong2 wv = *(const ulonglong2*)&s.wbuf[(w + 8 * i) * XPS + 4 * k0];
                        acc2[i] = fma2(xv.x, wv.x, acc2[i]);
                        acc2[i] = fma2(xv.y, wv.y, acc2[i]);
                    }
                }
#pragma unroll
                for (int i = 0; i < 5; i++) {
                    int j = w + 8 * i;
                    if (j < 36) s.dbl[lt][j] = hadd2(acc2[i]);
                }
            }
            __syncthreads();

            // ---- fused dt + scan (scalar, proven R9 form) ----
            {
                const int si0 = half * 8;
                float4 dwv = *(const float4*)(dtw + (ld * 128 + d) * 4);
                float dtbv = dtb[ld * 128 + d];
                float h[8];
#pragma unroll
                for (int si = 0; si < 8; si++) h[si] = 0.f;
                float* plane = &s.wbuf[half * 4096];

                if (afast) {
                    // A[i] = -(i+1): dA_i = r^(si0+1+i), r = exp(-dtv)
                    for (int t = 0; t < SEQ; t++) {
                        float4 dr = *(const float4*)(&s.dbl[t][0]);
                        float u = d4(dr, dwv) + dtbv;
                        float dtv = (u > 20.f) ? u : __logf(1.f + __expf(u));
                        float x = s.xc[t][d];
                        float dtx = dtv * x;
                        float4 B0 = *(const float4*)(&s.dbl[t][4 + si0]);
                        float4 B1 = *(const float4*)(&s.dbl[t][8 + si0]);
                        float4 C0 = *(const float4*)(&s.dbl[t][20 + si0]);
                        float4 C1 = *(const float4*)(&s.dbl[t][24 + si0]);
                        float r = __expf(-dtv);
                        float p;
                        if (half == 0) {
                            p = r;                       // r^1
                        } else {
                            float r2 = r * r, r4 = r2 * r2, r8 = r4 * r4;
                            p = r8 * r;                  // r^9
                        }
                        float y = 0.f;
#define SSTEPF(i, Bv, Cv)                                       \
    h[i] = p * h[i] + dtx * (Bv);                               \
    y += h[i] * (Cv);                                           \
    p *= r;
                        SSTEPF(0, B0.x, C0.x)  SSTEPF(1, B0.y, C0.y)
                        SSTEPF(2, B0.z, C0.z)  SSTEPF(3, B0.w, C0.w)
                        SSTEPF(4, B1.x, C1.x)  SSTEPF(5, B1.y, C1.y)
                        SSTEPF(6, B1.z, C1.z)  SSTEPF(7, B1.w, C1.w)
#undef SSTEPF
                        plane[t * 128 + d] = y;   // partial over 8 states
                    }
                } else {
                    // generic A fallback
                    const float* ar = alog + (ld * 128 + d) * 16 + si0;
                    float a[8];
#pragma unroll
                    for (int si = 0; si < 8; si += 4) {
                        float4 av = *(const float4*)(ar + si);
                        a[si] = -__expf(av.x); a[si + 1] = -__expf(av.y);
                        a[si + 2] = -__expf(av.z); a[si + 3] = -__expf(av.w);
                    }
                    for (int t = 0; t < SEQ; t++) {
                        float4 dr = *(const float4*)(&s.dbl[t][0]);
                        float u = d4(dr, dwv) + dtbv;
                        float dtv = (u > 20.f) ? u : __logf(1.f + __expf(u));
                        float x = s.xc[t][d];
                        float dtx = dtv * x;
                        float4 B0 = *(const float4*)(&s.dbl[t][4 + si0]);
                        float4 B1 = *(const float4*)(&s.dbl[t][8 + si0]);
                        float4 C0 = *(const float4*)(&s.dbl[t][20 + si0]);
                        float4 C1 = *(const float4*)(&s.dbl[t][24 + si0]);
                        float y = 0.f;
#define SSTEP(i, Bv, Cv)                                        \
    h[i] = __expf(dtv * a[i]) * h[i] + dtx * (Bv);              \
    y += h[i] * (Cv);
                        SSTEP(0, B0.x, C0.x)  SSTEP(1, B0.y, C0.y)
                        SSTEP(2, B0.z, C0.z)  SSTEP(3, B0.w, C0.w)
                        SSTEP(4, B1.x, C1.x)  SSTEP(5, B1.y, C1.y)
                        SSTEP(6, B1.z, C1.z)  SSTEP(7, B1.w, C1.w)
#undef SSTEP
                        plane[t * 128 + d] = y;
                    }
                }
            }
            __syncthreads();

            // ---- finalize in (c2,qt) mapping: combine halves, D*x, gate ----
            {
                float D0 = Dp[ld * 128 + c2];
                float D1 = Dp[ld * 128 + c2 + 64];
#pragma unroll
                for (int tt = 0; tt < 8; tt++) {
                    int t = tq0 + tt;
                    float y0 = s.wbuf[t * 128 + c2] + s.wbuf[4096 + t * 128 + c2];
                    float y1 = s.wbuf[t * 128 + c2 + 64] + s.wbuf[4096 + t * 128 + c2 + 64];
                    float x0 = s.xc[t][c2];
                    float x1 = s.xc[t][c2 + 64];
                    s.xc[t][c2] = (y0 + D0 * x0) * siluf(az0[tt]);
                    s.xc[t][c2 + 64] = (y1 + D1 * x1) * siluf(az1[tt]);
                }
            }
            __syncthreads();

            // ---- stage out_proj weights [64][128] -> wbuf[c][OPS] ----
            {
                const float4* g = (const float4*)(outw + ld * 64 * 128);
#pragma unroll
                for (int i = 0; i < 8; i++) {
                    int gi = tid + i * NT;           // 0..2047
                    int c = gi >> 5, kq = gi & 31;
                    *(float4*)&s.wbuf[c * OPS + 4 * kq] = g[gi];
                }
            }
            __syncthreads();

            // ---- out_proj (packed f32x2, small acc state): 2 c's x 4 t's ----
            {
                const int tq = tid >> 5;             // 0..7, warp-uniform
                const int c0 = tid & 31;             // bank step 4 at stride 132
                const int c1 = c0 + 32;
                u64 a0[4] = {0ULL, 0ULL, 0ULL, 0ULL};
                u64 a1[4] = {0ULL, 0ULL, 0ULL, 0ULL};
                const ulonglong2* W0 = (const ulonglong2*)&s.wbuf[c0 * OPS];
                const ulonglong2* W1 = (const ulonglong2*)&s.wbuf[c1 * OPS];
#pragma unroll 8
                for (int k0 = 0; k0 < 32; k0++) {
                    ulonglong2 w0 = W0[k0];
                    ulonglong2 w1 = W1[k0];
#pragma unroll
                    for (int tt = 0; tt < 4; tt++) {
                        ulonglong2 yv = *(const ulonglong2*)&s.xc[tq * 4 + tt][4 * k0];
                        a0[tt] = fma2(w0.x, yv.x, a0[tt]);
                        a0[tt] = fma2(w0.y, yv.y, a0[tt]);
                        a1[tt] = fma2(w1.x, yv.x, a1[tt]);
                        a1[tt] = fma2(w1.y, yv.y, a1[tt]);
                    }
                }
#pragma unroll
                for (int tt = 0; tt < 4; tt++) {
                    int t = tq * 4 + tt;
                    int rt = dir ? (31 - t) : t;
                    s.xe[rt][c0] += hadd2(a0[tt]);   // unique (rt,c) owner
                    s.xe[rt][c1] += hadd2(a1[tt]);
                }
            }
            __syncthreads();
        }
    }

    // ---- final: x = xe + x0 (recomputed), post-LN, project to scalar ----
    {
        float obr = s.ob[r8];
        float snrv = s.snr;
        int fzr = s.fz[r8];
        float v[8];
#pragma unroll
        for (int k = 0; k < 8; k++) {
            int kk = q8 * 8 + k;
            float x0v = obr * g_W1[kk] + snrv * g_W2[kk] + g_E[fzr][kk] + g_Bc[kk];
            v[k] = s.xe[r8][kk] + x0v;
        }
        float sum = 0.f;
#pragma unroll
        for (int k = 0; k < 8; k++) sum += v[k];
        sum += __shfl_xor_sync(0xffffffffu, sum, 1);
        sum += __shfl_xor_sync(0xffffffffu, sum, 2);
        sum += __shfl_xor_sync(0xffffffffu, sum, 4);
        float m = sum * (1.f / 64.f);
        float var = 0.f;
#pragma unroll
        for (int k = 0; k < 8; k++) { float dd = v[k] - m; var += dd * dd; }
        var += __shfl_xor_sync(0xffffffffu, var, 1);
        var += __shfl_xor_sync(0xffffffffu, var, 2);
        var += __shfl_xor_sync(0xffffffffu, var, 4);
        float rstd = rsqrtf(var * (1.f / 64.f) + 1e-5f);
        float acc = 0.f;
#pragma unroll
        for (int k = 0; k < 8; k++) {
            int kk = q8 * 8 + k;
            acc += ((v[k] - m) * rstd * pw[kk] + pb[kk]) * fw[kk];
        }
        acc += __shfl_xor_sync(0xffffffffu, acc, 1);
        acc += __shfl_xor_sync(0xffffffffu, acc, 2);
        acc += __shfl_xor_sync(0xffffffffu, acc, 4);
        if (q8 == 0) out[b * SEQ + r8] = acc + fb[0];
    }
}

extern "C" void kernel_launch(void* const* d_in, const int* in_sizes, int n_in,
                              void* d_out, int out_size) {
    // Disambiguate input ordering:
    //  dict order:      [ch, snr, frozen, emb, ...]  -> in_sizes[2] == 32768
    //  signature order: [ch, snr, emb, ..., frozen]  -> in_sizes[2] == 128
    const bool dictOrder = (in_sizes[2] == BATCH * SEQ);
    const int i_ch = 0, i_snr = 1;
    const int i_fz = dictOrder ? 2 : 24;
    const int base = dictOrder ? 3 : 2;
    const int i_emb = base + 0, i_l1w = base + 1, i_l1b = base + 2;
    const int i_l2w = base + 3, i_l2b = base + 4;
    const int i_inw = base + 5, i_inb = base + 6;
    const int i_blnw = base + 7, i_blnb = base + 8;
    const int i_inproj = base + 9, i_convw = base + 10, i_convb = base + 11;
    const int i_xproj = base + 12, i_dtw = base + 13, i_dtb = base + 14;
    const int i_alog = base + 15, i_D = base + 16, i_outproj = base + 17;
    const int i_pw = base + 18, i_pb = base + 19;
    const int i_fw = base + 20, i_fb = base + 21;

    const float* f_ch = (const float*)d_in[i_ch];
    const float* f_snr = (const float*)d_in[i_snr];
    const int* f_fz = (const int*)d_in[i_fz];

    setup_kernel<<<1, 64>>>(
        (const float*)d_in[i_inw], (const float*)d_in[i_inb],
        (const float*)d_in[i_l1w], (const float*)d_in[i_l1b],
        (const float*)d_in[i_l2w], (const float*)d_in[i_l2b],
        (const float*)d_in[i_emb], (const float*)d_in[i_alog]);

    size_t shbytes = sizeof(SmemT);
    cudaFuncSetAttribute(mamba_kernel,
                         cudaFuncAttributeMaxDynamicSharedMemorySize,
                         (int)shbytes);

    mamba_kernel<<<BATCH, NT, shbytes>>>(
        f_ch, f_snr, f_fz,
        (const float*)d_in[i_blnw], (const float*)d_in[i_blnb],
        (const float*)d_in[i_inproj], (const float*)d_in[i_convw],
        (const float*)d_in[i_convb], (const float*)d_in[i_xproj],
        (const float*)d_in[i_dtw], (const float*)d_in[i_dtb],
        (const float*)d_in[i_alog], (const float*)d_in[i_D],
        (const float*)d_in[i_outproj],
        (const float*)d_in[i_pw], (const float*)d_in[i_pb],
        (const float*)d_in[i_fw], (const float*)d_in[i_fb],
        (float*)d_out);
}

// round 13
// speedup vs baseline: 1.6366x; 1.0626x over previous
#include <cuda_runtime.h>

#define BATCH 1024
#define SEQ 32
#define DM 64
#define NL 4
#define DIN 128
#define XST 132   // padded float stride for xc rows
#define WST 68    // stride for in_proj weight rows (64 + 4)
#define XPS 132   // stride for xproj weight rows
#define OPS 132   // stride for out_proj weight rows (mult of 4 for float4)
#define WBN 17408 // wbuf floats = 256*68 (r/dtx planes @0, y planes @8192)
#define NT 256

typedef unsigned long long u64;

// ---- packed f32x2 helpers (sm_100+) ----
__device__ __forceinline__ u64 fma2(u64 a, u64 b, u64 c) {
    u64 d; asm("fma.rn.f32x2 %0, %1, %2, %3;" : "=l"(d) : "l"(a), "l"(b), "l"(c));
    return d;
}
__device__ __forceinline__ float hadd2(u64 v) {
    float lo, hi;
    asm("mov.b64 {%0, %1}, %2;" : "=f"(lo), "=f"(hi) : "l"(v));
    return lo + hi;
}

// Fused embedding parameters (computed once per launch by setup_kernel):
__device__ float g_W1[64];
__device__ float g_W2[64];
__device__ float g_Bc[64];
__device__ float g_E[2][64];
__device__ int   g_Afast;   // 1 if A_log == log(1..16) broadcast (integer A)

__global__ void setup_kernel(const float* __restrict__ inw,
                             const float* __restrict__ inb,
                             const float* __restrict__ l1w,
                             const float* __restrict__ l1b,
                             const float* __restrict__ l2w,
                             const float* __restrict__ l2b,
                             const float* __restrict__ emb,
                             const float* __restrict__ alog) {
    __shared__ int sbad;
    int c = threadIdx.x;
    if (c == 0) sbad = 0;
    __syncthreads();
    int bad = 0;
    for (int idx = c; idx < NL * 2 * DIN * 16; idx += 64) {
        int i = idx & 15;
        if (fabsf(alog[idx] - __logf((float)(i + 1))) > 1e-4f) bad = 1;
    }
    if (bad) atomicExch(&sbad, 1);
    __syncthreads();
    if (c == 0) g_Afast = sbad ? 0 : 1;

    if (c >= 64) return;
    const float* row = inw + c * 192;   // in_w is (64, 192) row-major
    float w1 = 0.f, w2 = 0.f, bb = inb[c], e0 = 0.f, e1 = 0.f;
    for (int k = 0; k < 64; k++) {
        float r0 = row[k], r1 = row[64 + k], r2 = row[128 + k];
        w1 += r0 * l1w[k];
        w2 += r1 * l2w[k];
        bb += r0 * l1b[k] + r1 * l2b[k];
        e0 += r2 * emb[k];
        e1 += r2 * emb[64 + k];
    }
    g_W1[c] = w1; g_W2[c] = w2; g_Bc[c] = bb;
    g_E[0][c] = e0; g_E[1][c] = e1;
}

struct SmemT {
    float wbuf[WBN];        // staged weights / r+dtx planes / y planes
    float xe[SEQ][DM];      // running residual stream
    float hln[SEQ][DM];     // layernormed input (shared by both dirs)
    float xc[SEQ][XST];     // raw x -> conv+silu x -> gated y' (in place)
    float dbl[SEQ][36];     // xproj output: [dt_r(4) | B(16) | C(16)]
    float ob[SEQ];
    int   fz[SEQ];
    float snr;
};

__device__ __forceinline__ float d4(float4 a, float4 b) {
    return a.x * b.x + a.y * b.y + a.z * b.z + a.w * b.w;
}
__device__ __forceinline__ float sigf(float x) {
    return __fdividef(1.f, 1.f + __expf(-x));
}
__device__ __forceinline__ float siluf(float x) { return x * sigf(x); }

__global__ __launch_bounds__(NT, 2) void mamba_kernel(
    const float* __restrict__ ob, const float* __restrict__ snr,
    const int* __restrict__ fz,
    const float* __restrict__ blnw, const float* __restrict__ blnb,
    const float* __restrict__ inproj, const float* __restrict__ convw,
    const float* __restrict__ convb, const float* __restrict__ xprojw,
    const float* __restrict__ dtw, const float* __restrict__ dtb,
    const float* __restrict__ alog, const float* __restrict__ Dp,
    const float* __restrict__ outw,
    const float* __restrict__ pw, const float* __restrict__ pb,
    const float* __restrict__ fw, const float* __restrict__ fb,
    float* __restrict__ out) {
    extern __shared__ unsigned char smem_raw[];
    SmemT& s = *reinterpret_cast<SmemT*>(smem_raw);

    const int tid = threadIdx.x;
    const int b = blockIdx.x;
    const int d = tid & 127;       // scan: channel (0..127)
    const int half = tid >> 7;     // scan: state half
    const int c2 = tid & 63;       // in_proj/conv/gate: channels c2, c2+64
    const int qt = tid >> 6;       // in_proj/conv/gate: time quarter (8 t's)
    const int tq0 = qt << 3;
    const int r8 = tid >> 3;       // LN row (0..31)
    const int q8 = tid & 7;        // LN lane within row
    const int afast = g_Afast;

    // ---- Phase 0: embedding -> xe ----
    if (tid < 32) {
        s.ob[tid] = ob[b * SEQ + tid];
        s.fz[tid] = fz[b * SEQ + tid];
    }
    if (tid == 0) s.snr = snr[b];
    __syncthreads();
#pragma unroll
    for (int i = 0; i < 8; i++) {
        int o = tid + i * NT;
        int t = o >> 6, c = o & 63;
        s.xe[t][c] = s.ob[t] * g_W1[c] + s.snr * g_W2[c] + g_E[s.fz[t]][c] + g_Bc[c];
    }
    __syncthreads();

    for (int l = 0; l < NL; l++) {
        // ---- LayerNorm: 8 threads per row, 8 elems each ----
        {
            float v[8];
            const float* xr = s.xe[r8];
#pragma unroll
            for (int k = 0; k < 8; k++) v[k] = xr[q8 * 8 + k];
            float sum = 0.f;
#pragma unroll
            for (int k = 0; k < 8; k++) sum += v[k];
            sum += __shfl_xor_sync(0xffffffffu, sum, 1);
            sum += __shfl_xor_sync(0xffffffffu, sum, 2);
            sum += __shfl_xor_sync(0xffffffffu, sum, 4);
            float m = sum * (1.f / 64.f);
            float var = 0.f;
#pragma unroll
            for (int k = 0; k < 8; k++) { float dd = v[k] - m; var += dd * dd; }
            var += __shfl_xor_sync(0xffffffffu, var, 1);
            var += __shfl_xor_sync(0xffffffffu, var, 2);
            var += __shfl_xor_sync(0xffffffffu, var, 4);
            float rstd = rsqrtf(var * (1.f / 64.f) + 1e-5f);
            const float* lw = blnw + l * 64;
            const float* lb = blnb + l * 64;
#pragma unroll
            for (int k = 0; k < 8; k++) {
                int kk = q8 * 8 + k;
                s.hln[r8][kk] = (v[k] - m) * rstd * lw[kk] + lb[kk];
            }
        }
        __syncthreads();

        for (int dir = 0; dir < 2; dir++) {
            const int ld = l * 2 + dir;
            float az0[8], az1[8];   // z columns (2 ch x 8 t), regs until gate

            // ---- stage Wx+Wz (256 rows x 64) into wbuf[row][WST] ----
            {
                const float4* g = (const float4*)(inproj + ld * 256 * 64);
#pragma unroll
                for (int i = 0; i < 16; i++) {
                    int gi = tid + i * NT;           // 0..4095
                    int rr = gi >> 4, j = gi & 15;
                    *(float4*)&s.wbuf[rr * WST + 4 * j] = g[gi];
                }
            }
            __syncthreads();

            // ---- fused in_proj (scalar, proven R9 form): 2 ch x 8 t ----
            float ax0[8], ax1[8];
            {
#pragma unroll
                for (int tt = 0; tt < 8; tt++) {
                    ax0[tt] = 0.f; ax1[tt] = 0.f; az0[tt] = 0.f; az1[tt] = 0.f;
                }
                const float* Wx0 = &s.wbuf[c2 * WST];
                const float* Wx1 = &s.wbuf[(c2 + 64) * WST];
                const float* Wz0 = &s.wbuf[(128 + c2) * WST];
                const float* Wz1 = &s.wbuf[(192 + c2) * WST];
#pragma unroll
                for (int k0 = 0; k0 < 16; k0++) {
                    float4 wx0 = *(const float4*)(Wx0 + 4 * k0);
                    float4 wx1 = *(const float4*)(Wx1 + 4 * k0);
                    float4 wz0 = *(const float4*)(Wz0 + 4 * k0);
                    float4 wz1 = *(const float4*)(Wz1 + 4 * k0);
#pragma unroll
                    for (int tt = 0; tt < 8; tt++) {
                        int t = tq0 + tt;
                        int rt = dir ? (31 - t) : t;
                        float4 h = *(const float4*)&s.hln[rt][4 * k0];  // broadcast
                        ax0[tt] += d4(h, wx0);
                        ax1[tt] += d4(h, wx1);
                        az0[tt] += d4(h, wz0);
                        az1[tt] += d4(h, wz1);
                    }
                }
                // publish raw x for cross-quarter conv boundary
#pragma unroll
                for (int tt = 0; tt < 8; tt++) {
                    s.xc[tq0 + tt][c2] = ax0[tt];
                    s.xc[tq0 + tt][c2 + 64] = ax1[tt];
                }
            }
            __syncthreads();

            // ---- read conv boundary preds (raw values of prev quarter) ----
            float pa0 = 0.f, pa1 = 0.f, pa2 = 0.f;   // channel c2
            float pb0 = 0.f, pb1 = 0.f, pb2 = 0.f;   // channel c2+64
            if (qt) {
                pa0 = s.xc[tq0 - 3][c2]; pa1 = s.xc[tq0 - 2][c2]; pa2 = s.xc[tq0 - 1][c2];
                pb0 = s.xc[tq0 - 3][c2 + 64]; pb1 = s.xc[tq0 - 2][c2 + 64]; pb2 = s.xc[tq0 - 1][c2 + 64];
            }
            __syncthreads();

            // ---- conv (k=4) + bias + silu, write in place; stage xproj wts ----
            {
                float4 cwa = *(const float4*)(convw + (ld * 128 + c2) * 4);
                float4 cwb = *(const float4*)(convw + (ld * 128 + c2 + 64) * 4);
                float cba = convb[ld * 128 + c2];
                float cbb = convb[ld * 128 + c2 + 64];
#pragma unroll
                for (int tt = 0; tt < 8; tt++) {
                    float ra = ax0[tt], rb = ax1[tt];
                    float va = cba + cwa.x * pa0 + cwa.y * pa1 + cwa.z * pa2 + cwa.w * ra;
                    float vb = cbb + cwb.x * pb0 + cwb.y * pb1 + cwb.z * pb2 + cwb.w * rb;
                    s.xc[tq0 + tt][c2] = siluf(va);
                    s.xc[tq0 + tt][c2 + 64] = siluf(vb);
                    pa0 = pa1; pa1 = pa2; pa2 = ra;
                    pb0 = pb1; pb1 = pb2; pb2 = rb;
                }
            }
            {
                const float4* g = (const float4*)(xprojw + ld * 36 * 128);
#pragma unroll
                for (int i = 0; i < 5; i++) {
                    int gi = tid + i * NT;           // 0..1279, guard 1152
                    if (gi < 1152) {
                        int j = gi >> 5, kq = gi & 31;
                        *(float4*)&s.wbuf[j * XPS + 4 * kq] = g[gi];
                    }
                }
            }
            __syncthreads();

            // ---- xproj (packed f32x2): warp owns j-set, lane owns t ----
            {
                const int w = tid >> 5;      // 0..7 (warp id)
                const int lt = tid & 31;     // lane = t
                u64 acc2[5] = {0ULL, 0ULL, 0ULL, 0ULL, 0ULL};
#pragma unroll 8
                for (int k0 = 0; k0 < 32; k0++) {
                    ulonglong2 xv = *(const ulonglong2*)&s.xc[lt][4 * k0];
#pragma unroll
                    for (int i = 0; i < 5; i++) {
                        ulonglong2 wv = *(const ulonglong2*)&s.wbuf[(w + 8 * i) * XPS + 4 * k0];
                        acc2[i] = fma2(xv.x, wv.x, acc2[i]);
                        acc2[i] = fma2(xv.y, wv.y, acc2[i]);
                    }
                }
#pragma unroll
                for (int i = 0; i < 5; i++) {
                    int j = w + 8 * i;
                    if (j < 36) s.dbl[lt][j] = hadd2(acc2[i]);
                }
            }
            __syncthreads();

            // ---- precompute r + dtx planes (dedup: once per (ch,t)) ----
            // r = exp(-softplus(u)) = 1/(1+e^u); dtx = softplus(u)*x
            // planes: wbuf[0 + t*128 + ch] = r, wbuf[4096 + t*128 + ch] = dtx
            if (afast) {
                float4 dw0 = *(const float4*)(dtw + (ld * 128 + c2) * 4);
                float4 dw1 = *(const float4*)(dtw + (ld * 128 + c2 + 64) * 4);
                float db0 = dtb[ld * 128 + c2];
                float db1 = dtb[ld * 128 + c2 + 64];
#pragma unroll
                for (int tt = 0; tt < 8; tt++) {
                    int t = tq0 + tt;
                    float4 dr = *(const float4*)(&s.dbl[t][0]);  // broadcast
                    float u0 = d4(dr, dw0) + db0;
                    float u1 = d4(dr, dw1) + db1;
                    float eu0 = __expf(u0), eu1 = __expf(u1);
                    float dtv0 = (u0 > 20.f) ? u0 : __logf(1.f + eu0);
                    float dtv1 = (u1 > 20.f) ? u1 : __logf(1.f + eu1);
                    float rr0 = __fdividef(1.f, 1.f + eu0);
                    float rr1 = __fdividef(1.f, 1.f + eu1);
                    s.wbuf[t * 128 + c2] = rr0;
                    s.wbuf[t * 128 + c2 + 64] = rr1;
                    s.wbuf[4096 + t * 128 + c2] = dtv0 * s.xc[t][c2];
                    s.wbuf[4096 + t * 128 + c2 + 64] = dtv1 * s.xc[t][c2 + 64];
                }
            }
            __syncthreads();

            // ---- scan, thread=(d,half): 8 states over all 32 t ----
            {
                const int si0 = half * 8;
                float h[8];
#pragma unroll
                for (int si = 0; si < 8; si++) h[si] = 0.f;
                float* plane = &s.wbuf[8192 + half * 4096];

                if (afast) {
                    // A[i] = -(i+1): dA_i = r^(si0+1+i); r, dtx precomputed
                    for (int t = 0; t < SEQ; t++) {
                        float r = s.wbuf[t * 128 + d];
                        float dtx = s.wbuf[4096 + t * 128 + d];
                        float4 B0 = *(const float4*)(&s.dbl[t][4 + si0]);
                        float4 B1 = *(const float4*)(&s.dbl[t][8 + si0]);
                        float4 C0 = *(const float4*)(&s.dbl[t][20 + si0]);
                        float4 C1 = *(const float4*)(&s.dbl[t][24 + si0]);
                        float p;
                        if (half == 0) {
                            p = r;                       // r^1
                        } else {
                            float r2 = r * r, r4 = r2 * r2, r8 = r4 * r4;
                            p = r8 * r;                  // r^9
                        }
                        float y = 0.f;
#define SSTEPF(i, Bv, Cv)                                       \
    h[i] = p * h[i] + dtx * (Bv);                               \
    y += h[i] * (Cv);                                           \
    p *= r;
                        SSTEPF(0, B0.x, C0.x)  SSTEPF(1, B0.y, C0.y)
                        SSTEPF(2, B0.z, C0.z)  SSTEPF(3, B0.w, C0.w)
                        SSTEPF(4, B1.x, C1.x)  SSTEPF(5, B1.y, C1.y)
                        SSTEPF(6, B1.z, C1.z)  SSTEPF(7, B1.w, C1.w)
#undef SSTEPF
                        plane[t * 128 + d] = y;   // partial over 8 states
                    }
                } else {
                    // generic A fallback (self-contained recompute)
                    float4 dwv = *(const float4*)(dtw + (ld * 128 + d) * 4);
                    float dtbv = dtb[ld * 128 + d];
                    const float* ar = alog + (ld * 128 + d) * 16 + si0;
                    float a[8];
#pragma unroll
                    for (int si = 0; si < 8; si += 4) {
                        float4 av = *(const float4*)(ar + si);
                        a[si] = -__expf(av.x); a[si + 1] = -__expf(av.y);
                        a[si + 2] = -__expf(av.z); a[si + 3] = -__expf(av.w);
                    }
                    for (int t = 0; t < SEQ; t++) {
                        float4 dr = *(const float4*)(&s.dbl[t][0]);
                        float u = d4(dr, dwv) + dtbv;
                        float dtv = (u > 20.f) ? u : __logf(1.f + __expf(u));
                        float x = s.xc[t][d];
                        float dtx = dtv * x;
                        float4 B0 = *(const float4*)(&s.dbl[t][4 + si0]);
                        float4 B1 = *(const float4*)(&s.dbl[t][8 + si0]);
                        float4 C0 = *(const float4*)(&s.dbl[t][20 + si0]);
                        float4 C1 = *(const float4*)(&s.dbl[t][24 + si0]);
                        float y = 0.f;
#define SSTEP(i, Bv, Cv)                                        \
    h[i] = __expf(dtv * a[i]) * h[i] + dtx * (Bv);              \
    y += h[i] * (Cv);
                        SSTEP(0, B0.x, C0.x)  SSTEP(1, B0.y, C0.y)
                        SSTEP(2, B0.z, C0.z)  SSTEP(3, B0.w, C0.w)
                        SSTEP(4, B1.x, C1.x)  SSTEP(5, B1.y, C1.y)
                        SSTEP(6, B1.z, C1.z)  SSTEP(7, B1.w, C1.w)
#undef SSTEP
                        plane[t * 128 + d] = y;
                    }
                }
            }
            __syncthreads();

            // ---- finalize in (c2,qt) mapping: combine halves, D*x, gate ----
            {
                float D0 = Dp[ld * 128 + c2];
                float D1 = Dp[ld * 128 + c2 + 64];
#pragma unroll
                for (int tt = 0; tt < 8; tt++) {
                    int t = tq0 + tt;
                    float y0 = s.wbuf[8192 + t * 128 + c2] + s.wbuf[12288 + t * 128 + c2];
                    float y1 = s.wbuf[8192 + t * 128 + c2 + 64] + s.wbuf[12288 + t * 128 + c2 + 64];
                    float x0 = s.xc[t][c2];
                    float x1 = s.xc[t][c2 + 64];
                    s.xc[t][c2] = (y0 + D0 * x0) * siluf(az0[tt]);
                    s.xc[t][c2 + 64] = (y1 + D1 * x1) * siluf(az1[tt]);
                }
            }
            __syncthreads();

            // ---- stage out_proj weights [64][128] -> wbuf[c][OPS] ----
            {
                const float4* g = (const float4*)(outw + ld * 64 * 128);
#pragma unroll
                for (int i = 0; i < 8; i++) {
                    int gi = tid + i * NT;           // 0..2047
                    int c = gi >> 5, kq = gi & 31;
                    *(float4*)&s.wbuf[c * OPS + 4 * kq] = g[gi];
                }
            }
            __syncthreads();

            // ---- out_proj (packed f32x2): 2 c's (lane, lane+32) x 4 t's ----
            {
                const int tq = tid >> 5;             // 0..7, warp-uniform
                const int c0 = tid & 31;             // bank step 4 at stride 132
                const int c1 = c0 + 32;
                u64 a0[4] = {0ULL, 0ULL, 0ULL, 0ULL};
                u64 a1[4] = {0ULL, 0ULL, 0ULL, 0ULL};
                const ulonglong2* W0 = (const ulonglong2*)&s.wbuf[c0 * OPS];
                const ulonglong2* W1 = (const ulonglong2*)&s.wbuf[c1 * OPS];
#pragma unroll 8
                for (int k0 = 0; k0 < 32; k0++) {
                    ulonglong2 w0 = W0[k0];
                    ulonglong2 w1 = W1[k0];
#pragma unroll
                    for (int tt = 0; tt < 4; tt++) {
                        ulonglong2 yv = *(const ulonglong2*)&s.xc[tq * 4 + tt][4 * k0];
                        a0[tt] = fma2(w0.x, yv.x, a0[tt]);
                        a0[tt] = fma2(w0.y, yv.y, a0[tt]);
                        a1[tt] = fma2(w1.x, yv.x, a1[tt]);
                        a1[tt] = fma2(w1.y, yv.y, a1[tt]);
                    }
                }
#pragma unroll
                for (int tt = 0; tt < 4; tt++) {
                    int t = tq * 4 + tt;
                    int rt = dir ? (31 - t) : t;
                    s.xe[rt][c0] += hadd2(a0[tt]);   // unique (rt,c) owner
                    s.xe[rt][c1] += hadd2(a1[tt]);
                }
            }
            __syncthreads();
        }
    }

    // ---- final: x = xe + x0 (recomputed), post-LN, project to scalar ----
    {
        float obr = s.ob[r8];
        float snrv = s.snr;
        int fzr = s.fz[r8];
        float v[8];
#pragma unroll
        for (int k = 0; k < 8; k++) {
            int kk = q8 * 8 + k;
            float x0v = obr * g_W1[kk] + snrv * g_W2[kk] + g_E[fzr][kk] + g_Bc[kk];
            v[k] = s.xe[r8][kk] + x0v;
        }
        float sum = 0.f;
#pragma unroll
        for (int k = 0; k < 8; k++) sum += v[k];
        sum += __shfl_xor_sync(0xffffffffu, sum, 1);
        sum += __shfl_xor_sync(0xffffffffu, sum, 2);
        sum += __shfl_xor_sync(0xffffffffu, sum, 4);
        float m = sum * (1.f / 64.f);
        float var = 0.f;
#pragma unroll
        for (int k = 0; k < 8; k++) { float dd = v[k] - m; var += dd * dd; }
        var += __shfl_xor_sync(0xffffffffu, var, 1);
        var += __shfl_xor_sync(0xffffffffu, var, 2);
        var += __shfl_xor_sync(0xffffffffu, var, 4);
        float rstd = rsqrtf(var * (1.f / 64.f) + 1e-5f);
        float acc = 0.f;
#pragma unroll
        for (int k = 0; k < 8; k++) {
            int kk = q8 * 8 + k;
            acc += ((v[k] - m) * rstd * pw[kk] + pb[kk]) * fw[kk];
        }
        acc += __shfl_xor_sync(0xffffffffu, acc, 1);
        acc += __shfl_xor_sync(0xffffffffu, acc, 2);
        acc += __shfl_xor_sync(0xffffffffu, acc, 4);
        if (q8 == 0) out[b * SEQ + r8] = acc + fb[0];
    }
}

extern "C" void kernel_launch(void* const* d_in, const int* in_sizes, int n_in,
                              void* d_out, int out_size) {
    // Disambiguate input ordering:
    //  dict order:      [ch, snr, frozen, emb, ...]  -> in_sizes[2] == 32768
    //  signature order: [ch, snr, emb, ..., frozen]  -> in_sizes[2] == 128
    const bool dictOrder = (in_sizes[2] == BATCH * SEQ);
    const int i_ch = 0, i_snr = 1;
    const int i_fz = dictOrder ? 2 : 24;
    const int base = dictOrder ? 3 : 2;
    const int i_emb = base + 0, i_l1w = base + 1, i_l1b = base + 2;
    const int i_l2w = base + 3, i_l2b = base + 4;
    const int i_inw = base + 5, i_inb = base + 6;
    const int i_blnw = base + 7, i_blnb = base + 8;
    const int i_inproj = base + 9, i_convw = base + 10, i_convb = base + 11;
    const int i_xproj = base + 12, i_dtw = base + 13, i_dtb = base + 14;
    const int i_alog = base + 15, i_D = base + 16, i_outproj = base + 17;
    const int i_pw = base + 18, i_pb = base + 19;
    const int i_fw = base + 20, i_fb = base + 21;

    const float* f_ch = (const float*)d_in[i_ch];
    const float* f_snr = (const float*)d_in[i_snr];
    const int* f_fz = (const int*)d_in[i_fz];

    setup_kernel<<<1, 64>>>(
        (const float*)d_in[i_inw], (const float*)d_in[i_inb],
        (const float*)d_in[i_l1w], (const float*)d_in[i_l1b],
        (const float*)d_in[i_l2w], (const float*)d_in[i_l2b],
        (const float*)d_in[i_emb], (const float*)d_in[i_alog]);

    size_t shbytes = sizeof(SmemT);
    cudaFuncSetAttribute(mamba_kernel,
                         cudaFuncAttributeMaxDynamicSharedMemorySize,
                         (int)shbytes);

    mamba_kernel<<<BATCH, NT, shbytes>>>(
        f_ch, f_snr, f_fz,
        (const float*)d_in[i_blnw], (const float*)d_in[i_blnb],
        (const float*)d_in[i_inproj], (const float*)d_in[i_convw],
        (const float*)d_in[i_convb], (const float*)d_in[i_xproj],
        (const float*)d_in[i_dtw], (const float*)d_in[i_dtb],
        (const float*)d_in[i_alog], (const float*)d_in[i_D],
        (const float*)d_in[i_outproj],
        (const float*)d_in[i_pw], (const float*)d_in[i_pb],
        (const float*)d_in[i_fw], (const float*)d_in[i_fb],
        (float*)d_out);
}